// round 1
// baseline (speedup 1.0000x reference)
#include <cuda_runtime.h>
#include <cuda_bf16.h>
#include <cstdint>

// Problem constants (fixed by the dataset: B=8, H=W=128, Cin=128, Cout=256,
// KSIZE=3, STRIDE=2, PAD=1, DIL=1  ->  OH=OW=64, M=32768, K=9*128=1152)
#define BATCH 8
#define H_IN 128
#define W_IN 128
#define CIN 128
#define COUT 256
#define OHW 64                 // OH = OW = 64
#define M_TOTAL (BATCH * OHW * OHW)   // 32768
#define FEATS_OUT_ELEMS ((size_t)M_TOTAL * COUT)   // 8388608
#define COORD_OUT_ELEMS ((size_t)M_TOTAL * 3)      // 98304

// GEMM tiling
#define BM 128
#define BN 128
#define BK 8
#define TM 8
#define TN 8
#define NTHREADS 256

// Implicit-GEMM conv: out[p, n] = sum_{tap, c} A[p, tap*128+c] * W[tap, c, n]
// A[p, k] is a gathered (halo, zero-padded) read of feats.
__global__ __launch_bounds__(NTHREADS, 2)
void conv3x3s2_kernel(const float* __restrict__ feats,
                      const float* __restrict__ weight,
                      float* __restrict__ out)
{
    const int mblk = blockIdx.x;        // 0..255  (M / BM)
    const int nblk = blockIdx.y;        // 0..1    (COUT / BN)
    const int tid  = threadIdx.x;

    __shared__ float As[BK][BM];
    __shared__ float Bs[BK][BN];

    // ---- A loader mapping: 256 threads cover 128 rows x 8 k (1 float4 each)
    const int lm  = tid >> 1;           // pixel row within tile: 0..127
    const int lc4 = tid & 1;            // which float4 of the 8-wide k chunk
    const int p   = mblk * BM + lm;     // output pixel index
    const int b   = p >> 12;            // 4096 pixels per batch
    const int s   = p & 4095;
    const int oy  = (s >> 6) << 1;      // input-space center y (stride 2)
    const int ox  = (s & 63) << 1;

    // ---- B loader mapping: 256 threads cover 8 k-rows x 128 n (1 float4 each)
    const int lk = tid >> 5;            // 0..7
    const int ln = (tid & 31) << 2;     // 0,4,...,124

    // ---- compute-thread tile mapping
    const int ty = tid >> 4;            // 0..15 -> m
    const int tx = tid & 15;            // 0..15 -> n
    const int tm0 = ty * TM;
    const int tn0 = tx * TN;

    float acc[TM][TN];
    #pragma unroll
    for (int i = 0; i < TM; ++i)
        #pragma unroll
        for (int j = 0; j < TN; ++j)
            acc[i][j] = 0.f;

    const float* wbase = weight + nblk * BN;    // [9][CIN][COUT] row-major

    #pragma unroll 1
    for (int tap = 0; tap < 9; ++tap) {
        const int dy = tap / 3 - 1;
        const int dx = tap % 3 - 1;
        const int iy = oy + dy;
        const int ix = ox + dx;
        const bool valid = (iy >= 0) && (iy < H_IN) && (ix >= 0) && (ix < W_IN);
        const float* arow = feats + (((b * H_IN + iy) * W_IN + ix) * CIN);
        const float* brow = wbase + (size_t)tap * CIN * COUT;

        #pragma unroll 1
        for (int kc = 0; kc < CIN; kc += BK) {
            // global loads (issued before barrier; independent of prior compute)
            float4 av = make_float4(0.f, 0.f, 0.f, 0.f);
            if (valid)
                av = *reinterpret_cast<const float4*>(arow + kc + lc4 * 4);
            const float4 bv =
                *reinterpret_cast<const float4*>(brow + (size_t)(kc + lk) * COUT + ln);

            __syncthreads();                       // previous tile fully consumed
            const int kb = lc4 * 4;
            As[kb + 0][lm] = av.x;
            As[kb + 1][lm] = av.y;
            As[kb + 2][lm] = av.z;
            As[kb + 3][lm] = av.w;
            *reinterpret_cast<float4*>(&Bs[lk][ln]) = bv;
            __syncthreads();

            #pragma unroll
            for (int kk = 0; kk < BK; ++kk) {
                float a[TM], bb[TN];
                *reinterpret_cast<float4*>(&a[0]) =
                    *reinterpret_cast<const float4*>(&As[kk][tm0]);
                *reinterpret_cast<float4*>(&a[4]) =
                    *reinterpret_cast<const float4*>(&As[kk][tm0 + 4]);
                *reinterpret_cast<float4*>(&bb[0]) =
                    *reinterpret_cast<const float4*>(&Bs[kk][tn0]);
                *reinterpret_cast<float4*>(&bb[4]) =
                    *reinterpret_cast<const float4*>(&Bs[kk][tn0 + 4]);
                #pragma unroll
                for (int i = 0; i < TM; ++i)
                    #pragma unroll
                    for (int j = 0; j < TN; ++j)
                        acc[i][j] = fmaf(a[i], bb[j], acc[i][j]);
            }
        }
    }

    // ---- epilogue: out_feats[p, n], row length COUT
    const int n0 = nblk * BN + tn0;
    #pragma unroll
    for (int i = 0; i < TM; ++i) {
        const int pr = mblk * BM + tm0 + i;
        float* orow = out + (size_t)pr * COUT + n0;
        float4 v0 = make_float4(acc[i][0], acc[i][1], acc[i][2], acc[i][3]);
        float4 v1 = make_float4(acc[i][4], acc[i][5], acc[i][6], acc[i][7]);
        *reinterpret_cast<float4*>(orow)     = v0;
        *reinterpret_cast<float4*>(orow + 4) = v1;
    }
}

// out_coords (as float32 values) + alpha_upper tail.
__global__ void coords_kernel(const float* __restrict__ alpha,
                              float* __restrict__ out,
                              int write_alpha)
{
    const int idx = blockIdx.x * blockDim.x + threadIdx.x;
    if (idx < M_TOTAL) {
        const int b  = idx >> 12;
        const int s  = idx & 4095;
        const int oy = s >> 6;
        const int ox = s & 63;
        float* row = out + FEATS_OUT_ELEMS + (size_t)idx * 3;
        row[0] = (float)b;
        row[1] = (float)oy;
        row[2] = (float)ox;
    }
    if (idx == 0 && write_alpha)
        out[FEATS_OUT_ELEMS + COORD_OUT_ELEMS] = alpha[0];
}

extern "C" void kernel_launch(void* const* d_in, const int* in_sizes, int n_in,
                              void* d_out, int out_size)
{
    const float* feats  = (const float*)d_in[0];   // (B*H*W, Cin) f32
    const float* weight = (const float*)d_in[1];   // (9, Cin, Cout) f32
    const float* alpha  = (const float*)d_in[2];   // (1,) f32
    // d_in[3] = coords (full dense grid, implied), d_in[4..6] = H, W, B scalars

    float* out = (float*)d_out;

    dim3 grid(M_TOTAL / BM, COUT / BN);   // (256, 2)
    conv3x3s2_kernel<<<grid, NTHREADS>>>(feats, weight, out);

    // Write coords/alpha only if the output buffer actually includes them
    // (concat layout: feats | coords | alpha).
    if ((size_t)out_size >= FEATS_OUT_ELEMS + COORD_OUT_ELEMS) {
        const int write_alpha =
            ((size_t)out_size >= FEATS_OUT_ELEMS + COORD_OUT_ELEMS + 1) ? 1 : 0;
        coords_kernel<<<(M_TOTAL + 255) / 256, 256>>>(alpha, out, write_alpha);
    }
}

// round 3
// speedup vs baseline: 2.1495x; 2.1495x over previous
#include <cuda_runtime.h>
#include <cuda_bf16.h>
#include <cstdint>

// ---------------- problem constants ----------------
#define CIN 128
#define COUT 256
#define M_TOTAL 32768                      // 8 * 64 * 64
#define K_TOTAL 1152                       // 9 * 128
#define FEATS_OUT_ELEMS ((size_t)M_TOTAL * COUT)
#define COORD_OUT_ELEMS ((size_t)M_TOTAL * 3)

// ---------------- GEMM config ----------------
#define BM 128
#define BN 128
#define BK 32                 // bf16 k per chunk
#define NCHUNK 36             // K_TOTAL / BK
#define NTHREADS 256

// smem stage layout (bytes), per stage:
//   +0      Ahi [128][40] bf16   (10240 B)  (stride 40 halves = 80 B)
//   +10240  Alo
//   +20480  Bhi [128][40] bf16   (B stored [n][k])
//   +30720  Blo
#define LDS_STRIDE_B 80
#define OFF_ALO 10240
#define OFF_BHI 20480
#define OFF_BLO 30720
#define STAGE_BYTES 40960
#define SMEM_TOTAL (2 * STAGE_BYTES)   // 81920

// weight scratch, transposed + split: [n][k] bf16
__device__ __align__(16) __nv_bfloat16 g_Whi[COUT * K_TOTAL];
__device__ __align__(16) __nv_bfloat16 g_Wlo[COUT * K_TOTAL];

// ---------------- helpers ----------------
__device__ __forceinline__ uint32_t smem_u32(const void* p) {
    uint32_t a;
    asm("{ .reg .u64 t; cvta.to.shared.u64 t, %1; cvt.u32.u64 %0, t; }" : "=r"(a) : "l"(p));
    return a;
}
__device__ __forceinline__ void cp_async16(uint32_t dst, const void* src) {
    asm volatile("cp.async.cg.shared.global [%0], [%1], 16;" :: "r"(dst), "l"(src) : "memory");
}
__device__ __forceinline__ void cp_commit() {
    asm volatile("cp.async.commit_group;" ::: "memory");
}
__device__ __forceinline__ void cp_wait_all() {
    asm volatile("cp.async.wait_group 0;" ::: "memory");
}
__device__ __forceinline__ void ldsm_x4(uint32_t& r0, uint32_t& r1, uint32_t& r2, uint32_t& r3,
                                        uint32_t addr) {
    asm volatile("ldmatrix.sync.aligned.m8n8.x4.shared.b16 {%0,%1,%2,%3}, [%4];"
                 : "=r"(r0), "=r"(r1), "=r"(r2), "=r"(r3) : "r"(addr));
}
__device__ __forceinline__ void mma16816(float* c, const uint32_t* a, uint32_t b0, uint32_t b1) {
    asm volatile("mma.sync.aligned.m16n8k16.row.col.f32.bf16.bf16.f32 "
                 "{%0,%1,%2,%3}, {%4,%5,%6,%7}, {%8,%9}, {%0,%1,%2,%3};"
                 : "+f"(c[0]), "+f"(c[1]), "+f"(c[2]), "+f"(c[3])
                 : "r"(a[0]), "r"(a[1]), "r"(a[2]), "r"(a[3]), "r"(b0), "r"(b1));
}
__device__ __forceinline__ uint32_t pack_hi(float x, float y) {
    __nv_bfloat162 h = __floats2bfloat162_rn(x, y);
    return *reinterpret_cast<uint32_t*>(&h);
}
__device__ __forceinline__ uint32_t pack_lo(float x, float y, uint32_t hi) {
    __nv_bfloat162 h = *reinterpret_cast<__nv_bfloat162*>(&hi);
    __nv_bfloat162 lo = __floats2bfloat162_rn(x - __bfloat162float(h.x),
                                              y - __bfloat162float(h.y));
    return *reinterpret_cast<uint32_t*>(&lo);
}

// ---------------- weight split/transpose ----------------
// weight[k][n] fp32  ->  g_Whi/g_Wlo [n][k] bf16
__global__ void wconv_kernel(const float* __restrict__ w) {
    int idx = blockIdx.x * 256 + threadIdx.x;
    if (idx < K_TOTAL * COUT) {
        int k = idx >> 8;
        int n = idx & 255;
        float x = w[idx];
        __nv_bfloat16 h = __float2bfloat16(x);
        g_Whi[n * K_TOTAL + k] = h;
        g_Wlo[n * K_TOTAL + k] = __float2bfloat16(x - __bfloat162float(h));
    }
}

// ---------------- main GEMM kernel ----------------
__global__ __launch_bounds__(NTHREADS, 1)
void conv_mma_kernel(const float* __restrict__ feats,
                     const float* __restrict__ alpha,
                     float* __restrict__ out)
{
    extern __shared__ char smem[];
    const uint32_t sb = smem_u32(smem);
    const int tid = threadIdx.x;
    const int w = tid >> 5, l = tid & 31;
    const int mblk = blockIdx.x, nblk = blockIdx.y;
    const int wm = w & 3, wn = w >> 2;

    // coords + alpha tail (once, from the nblk==0 plane)
    if (nblk == 0) {
        if (tid < 128) {
            int p = mblk * 128 + tid;
            float* row = out + FEATS_OUT_ELEMS + (size_t)p * 3;
            row[0] = (float)(p >> 12);
            row[1] = (float)((p & 4095) >> 6);
            row[2] = (float)(p & 63);
        }
        if (mblk == 0 && tid == 128)
            out[FEATS_OUT_ELEMS + COORD_OUT_ELEMS] = alpha[0];
    }

    // ---- A loader geometry: thread t -> tile row ar, 16 floats at col ac0
    const int ar  = tid >> 1;
    const int ac0 = (tid & 1) * 16;
    const int p   = mblk * 128 + ar;
    const int ab  = p >> 12;
    const int aoy = ((p & 4095) >> 6) << 1;
    const int aox = (p & 63) << 1;

    // ---- B loader geometry: thread t -> B row br, two 16B segs
    const int br    = tid >> 1;
    const int bseg0 = (tid & 1) * 2;
    const int bgn   = nblk * 128 + br;

    float acc[2][8][4];
    #pragma unroll
    for (int i = 0; i < 2; ++i)
        #pragma unroll
        for (int j = 0; j < 8; ++j)
            #pragma unroll
            for (int q = 0; q < 4; ++q) acc[i][j][q] = 0.f;

    // ---- prologue: chunk 0
    {
        // A: tap 0 (dy=-1,dx=-1), kc=0
        const int iy = aoy - 1, ix = aox - 1;
        const bool valid = ((unsigned)iy < 128u) && ((unsigned)ix < 128u);
        float4 v[4] = {};
        if (valid) {
            const float* ap = feats + ((size_t)(((ab << 7) + iy) << 7) + ix) * CIN + ac0;
            #pragma unroll
            for (int j = 0; j < 4; ++j) v[j] = reinterpret_cast<const float4*>(ap)[j];
        }
        char* arow_hi = smem + (size_t)ar * LDS_STRIDE_B + ac0 * 2;
        #pragma unroll
        for (int j = 0; j < 4; ++j) {
            uint32_t h0 = pack_hi(v[j].x, v[j].y), h1 = pack_hi(v[j].z, v[j].w);
            uint32_t l0 = pack_lo(v[j].x, v[j].y, h0), l1 = pack_lo(v[j].z, v[j].w, h1);
            *reinterpret_cast<uint2*>(arow_hi + j * 8)           = make_uint2(h0, h1);
            *reinterpret_cast<uint2*>(arow_hi + OFF_ALO + j * 8) = make_uint2(l0, l1);
        }
        // B: cp.async, chunk 0 (koff = 0)
        const char* srch = (const char*)(g_Whi + (size_t)bgn * K_TOTAL) + bseg0 * 16;
        const char* srcl = (const char*)(g_Wlo + (size_t)bgn * K_TOTAL) + bseg0 * 16;
        uint32_t bdst = sb + OFF_BHI + br * LDS_STRIDE_B + bseg0 * 16;
        cp_async16(bdst,                  srch);
        cp_async16(bdst + 16,             srch + 16);
        cp_async16(bdst + (OFF_BLO - OFF_BHI),      srcl);
        cp_async16(bdst + (OFF_BLO - OFF_BHI) + 16, srcl + 16);
        cp_commit();
    }

    // ---- main loop ----
    #pragma unroll 1
    for (int c = 0; c < NCHUNK; ++c) {
        const int st = c & 1;
        const bool have = (c + 1 < NCHUNK);

        // LDG A(c+1) into regs (long latency, covered by compute below)
        float4 v[4] = {};
        if (have) {
            const int nc = c + 1, tap = nc >> 2, kc = (nc & 3) << 5;
            const int iy = aoy + tap / 3 - 1, ix = aox + tap % 3 - 1;
            if (((unsigned)iy < 128u) && ((unsigned)ix < 128u)) {
                const float* ap = feats +
                    ((size_t)(((ab << 7) + iy) << 7) + ix) * CIN + kc + ac0;
                #pragma unroll
                for (int j = 0; j < 4; ++j) v[j] = reinterpret_cast<const float4*>(ap)[j];
            }
        }

        cp_wait_all();
        __syncthreads();

        // issue B cp.async for (c+1) into the other stage
        if (have) {
            const int nc = c + 1, tap = nc >> 2, kc = (nc & 3) << 5;
            const int nst = nc & 1;
            const uint32_t bko = (uint32_t)tap * 128 + kc;
            const char* srch = (const char*)(g_Whi + (size_t)bgn * K_TOTAL + bko) + bseg0 * 16;
            const char* srcl = (const char*)(g_Wlo + (size_t)bgn * K_TOTAL + bko) + bseg0 * 16;
            uint32_t bdst = sb + nst * STAGE_BYTES + OFF_BHI + br * LDS_STRIDE_B + bseg0 * 16;
            cp_async16(bdst,      srch);
            cp_async16(bdst + 16, srch + 16);
            cp_async16(bdst + (OFF_BLO - OFF_BHI),      srcl);
            cp_async16(bdst + (OFF_BLO - OFF_BHI) + 16, srcl + 16);
            cp_commit();
        }

        // ---- compute chunk c from stage st ----
        {
            const uint32_t a_s = sb + st * STAGE_BYTES;
            #pragma unroll
            for (int k16 = 0; k16 < 2; ++k16) {
                const int kb = k16 * 16;
                // A fragments (hi & lo) for both m16 tiles
                uint32_t ahi[2][4], alo[2][4];
                #pragma unroll
                for (int mt = 0; mt < 2; ++mt) {
                    const int arow = wm * 32 + mt * 16 + (l & 15);
                    const int acol = kb + (l >> 4) * 8;
                    const uint32_t aaddr = a_s + arow * LDS_STRIDE_B + acol * 2;
                    ldsm_x4(ahi[mt][0], ahi[mt][1], ahi[mt][2], ahi[mt][3], aaddr);
                    ldsm_x4(alo[mt][0], alo[mt][1], alo[mt][2], alo[mt][3], aaddr + OFF_ALO);
                }
                #pragma unroll
                for (int np = 0; np < 4; ++np) {
                    const int brow = wn * 64 + np * 16 + ((l >> 4) << 3) + (l & 7);
                    const int bcol = kb + ((l >> 3) & 1) * 8;
                    const uint32_t baddr = a_s + OFF_BHI + brow * LDS_STRIDE_B + bcol * 2;
                    uint32_t bh[4], bl[4];
                    ldsm_x4(bh[0], bh[1], bh[2], bh[3], baddr);
                    ldsm_x4(bl[0], bl[1], bl[2], bl[3], baddr + (OFF_BLO - OFF_BHI));
                    #pragma unroll
                    for (int mt = 0; mt < 2; ++mt) {
                        #pragma unroll
                        for (int sub = 0; sub < 2; ++sub) {
                            float* a4 = acc[mt][np * 2 + sub];
                            mma16816(a4, ahi[mt], bh[sub * 2], bh[sub * 2 + 1]);
                            mma16816(a4, ahi[mt], bl[sub * 2], bl[sub * 2 + 1]);
                            mma16816(a4, alo[mt], bh[sub * 2], bh[sub * 2 + 1]);
                        }
                    }
                }
            }
        }

        // ---- convert + STS A(c+1) into the other stage ----
        if (have) {
            const int nst = (c + 1) & 1;
            char* arow_hi = smem + (size_t)nst * STAGE_BYTES +
                            (size_t)ar * LDS_STRIDE_B + ac0 * 2;
            #pragma unroll
            for (int j = 0; j < 4; ++j) {
                uint32_t h0 = pack_hi(v[j].x, v[j].y), h1 = pack_hi(v[j].z, v[j].w);
                uint32_t l0 = pack_lo(v[j].x, v[j].y, h0), l1 = pack_lo(v[j].z, v[j].w, h1);
                *reinterpret_cast<uint2*>(arow_hi + j * 8)           = make_uint2(h0, h1);
                *reinterpret_cast<uint2*>(arow_hi + OFF_ALO + j * 8) = make_uint2(l0, l1);
            }
        }
    }

    // ---- epilogue ----
    const int row_base = mblk * 128 + wm * 32 + (l >> 2);
    const int col_base = nblk * 128 + wn * 64 + (l & 3) * 2;
    #pragma unroll
    for (int mt = 0; mt < 2; ++mt) {
        #pragma unroll
        for (int nt = 0; nt < 8; ++nt) {
            const int r0 = row_base + mt * 16;
            const int cc = col_base + nt * 8;
            float* o0 = out + (size_t)r0 * COUT + cc;
            float* o1 = out + (size_t)(r0 + 8) * COUT + cc;
            *reinterpret_cast<float2*>(o0) = make_float2(acc[mt][nt][0], acc[mt][nt][1]);
            *reinterpret_cast<float2*>(o1) = make_float2(acc[mt][nt][2], acc[mt][nt][3]);
        }
    }
}

// ---------------- launch ----------------
extern "C" void kernel_launch(void* const* d_in, const int* in_sizes, int n_in,
                              void* d_out, int out_size)
{
    const float* feats  = (const float*)d_in[0];
    const float* weight = (const float*)d_in[1];
    const float* alpha  = (const float*)d_in[2];
    float* out = (float*)d_out;

    cudaFuncSetAttribute(conv_mma_kernel,
                         cudaFuncAttributeMaxDynamicSharedMemorySize, SMEM_TOTAL);

    wconv_kernel<<<(K_TOTAL * COUT + 255) / 256, 256>>>(weight);
    dim3 grid(M_TOTAL / BM, COUT / BN);   // (256, 2)
    conv_mma_kernel<<<grid, NTHREADS, SMEM_TOTAL>>>(feats, alpha, out);
}

// round 4
// speedup vs baseline: 2.3779x; 1.1062x over previous
#include <cuda_runtime.h>
#include <cuda_bf16.h>
#include <cstdint>

// ---------------- problem constants ----------------
#define CIN 128
#define COUT 256
#define M_TOTAL 32768                      // 8 * 64 * 64
#define K_TOTAL 1152                       // 9 * 128
#define FEATS_OUT_ELEMS ((size_t)M_TOTAL * COUT)
#define COORD_OUT_ELEMS ((size_t)M_TOTAL * 3)

// ---------------- GEMM config ----------------
#define BM 128
#define BN 64
#define BK 32                 // bf16 k per chunk
#define NCHUNK 36             // K_TOTAL / BK
#define NTHREADS 256

// smem stage layout (bytes), stride 80B rows (conflict-free for ldmatrix):
//   +0      Ahi [128][40] bf16   (10240 B)
//   +10240  Alo [128][40]
//   +20480  Bhi [64][40]         ( 5120 B)  (B stored [n][k])
//   +25600  Blo [64][40]
#define LDS_STRIDE_B 80
#define OFF_ALO 10240
#define OFF_BHI 20480
#define OFF_BLO 25600
#define STAGE_BYTES 30720
#define SMEM_TOTAL (2 * STAGE_BYTES)   // 61440 -> 2 CTAs/SM

// weight scratch, transposed + split: [n][k] bf16
__device__ __align__(16) __nv_bfloat16 g_Whi[COUT * K_TOTAL];
__device__ __align__(16) __nv_bfloat16 g_Wlo[COUT * K_TOTAL];

// ---------------- helpers ----------------
__device__ __forceinline__ uint32_t smem_u32(const void* p) {
    uint32_t a;
    asm("{ .reg .u64 t; cvta.to.shared.u64 t, %1; cvt.u32.u64 %0, t; }" : "=r"(a) : "l"(p));
    return a;
}
__device__ __forceinline__ void cp_async16(uint32_t dst, const void* src) {
    asm volatile("cp.async.cg.shared.global [%0], [%1], 16;" :: "r"(dst), "l"(src) : "memory");
}
__device__ __forceinline__ void cp_commit() {
    asm volatile("cp.async.commit_group;" ::: "memory");
}
__device__ __forceinline__ void cp_wait_all() {
    asm volatile("cp.async.wait_group 0;" ::: "memory");
}
__device__ __forceinline__ void ldsm_x4(uint32_t& r0, uint32_t& r1, uint32_t& r2, uint32_t& r3,
                                        uint32_t addr) {
    asm volatile("ldmatrix.sync.aligned.m8n8.x4.shared.b16 {%0,%1,%2,%3}, [%4];"
                 : "=r"(r0), "=r"(r1), "=r"(r2), "=r"(r3) : "r"(addr));
}
__device__ __forceinline__ void mma16816(float* c, const uint32_t* a, uint32_t b0, uint32_t b1) {
    asm volatile("mma.sync.aligned.m16n8k16.row.col.f32.bf16.bf16.f32 "
                 "{%0,%1,%2,%3}, {%4,%5,%6,%7}, {%8,%9}, {%0,%1,%2,%3};"
                 : "+f"(c[0]), "+f"(c[1]), "+f"(c[2]), "+f"(c[3])
                 : "r"(a[0]), "r"(a[1]), "r"(a[2]), "r"(a[3]), "r"(b0), "r"(b1));
}
__device__ __forceinline__ uint32_t pack_hi(float x, float y) {
    __nv_bfloat162 h = __floats2bfloat162_rn(x, y);
    return *reinterpret_cast<uint32_t*>(&h);
}
__device__ __forceinline__ uint32_t pack_lo(float x, float y, uint32_t hi) {
    __nv_bfloat162 h = *reinterpret_cast<__nv_bfloat162*>(&hi);
    __nv_bfloat162 lo = __floats2bfloat162_rn(x - __bfloat162float(h.x),
                                              y - __bfloat162float(h.y));
    return *reinterpret_cast<uint32_t*>(&lo);
}

// ---------------- weight split/transpose ----------------
// weight[k][n] fp32  ->  g_Whi/g_Wlo [n][k] bf16
__global__ void wconv_kernel(const float* __restrict__ w) {
    int idx = blockIdx.x * 256 + threadIdx.x;
    if (idx < K_TOTAL * COUT) {
        int k = idx >> 8;
        int n = idx & 255;
        float x = w[idx];
        __nv_bfloat16 h = __float2bfloat16(x);
        g_Whi[n * K_TOTAL + k] = h;
        g_Wlo[n * K_TOTAL + k] = __float2bfloat16(x - __bfloat162float(h));
    }
}

// ---------------- main GEMM kernel ----------------
__global__ __launch_bounds__(NTHREADS, 2)
void conv_mma_kernel(const float* __restrict__ feats,
                     const float* __restrict__ alpha,
                     float* __restrict__ out)
{
    extern __shared__ char smem[];
    const uint32_t sb = smem_u32(smem);
    const int tid = threadIdx.x;
    const int w = tid >> 5, l = tid & 31;
    const int mblk = blockIdx.x, nblk = blockIdx.y;
    const int wm = w & 3, wn = w >> 2;      // 4 m-warps x 2 n-warps, warp tile 32x32

    // coords + alpha tail (once, from the nblk==0 plane)
    if (nblk == 0) {
        if (tid < 128) {
            int p = mblk * 128 + tid;
            float* row = out + FEATS_OUT_ELEMS + (size_t)p * 3;
            row[0] = (float)(p >> 12);
            row[1] = (float)((p & 4095) >> 6);
            row[2] = (float)(p & 63);
        }
        if (mblk == 0 && tid == 128)
            out[FEATS_OUT_ELEMS + COORD_OUT_ELEMS] = alpha[0];
    }

    // ---- A loader geometry: thread t -> tile row ar, 16 floats at col ac0
    const int ar  = tid >> 1;
    const int ac0 = (tid & 1) * 16;
    const int p   = mblk * 128 + ar;
    const int ab  = p >> 12;
    const int aoy = ((p & 4095) >> 6) << 1;
    const int aox = (p & 63) << 1;

    // ---- B loader geometry: thread t -> B row br (0..63), one 16B seg per matrix
    const int br   = tid >> 2;
    const int bseg = tid & 3;
    const int bgn  = nblk * 64 + br;

    float acc[2][4][4];
    #pragma unroll
    for (int i = 0; i < 2; ++i)
        #pragma unroll
        for (int j = 0; j < 4; ++j)
            #pragma unroll
            for (int q = 0; q < 4; ++q) acc[i][j][q] = 0.f;

    // ---- prologue: chunk 0
    {
        // A: tap 0 (dy=-1,dx=-1), kc=0
        const int iy = aoy - 1, ix = aox - 1;
        const bool valid = ((unsigned)iy < 128u) && ((unsigned)ix < 128u);
        float4 v[4] = {};
        if (valid) {
            const float* ap = feats + ((size_t)(((ab << 7) + iy) << 7) + ix) * CIN + ac0;
            #pragma unroll
            for (int j = 0; j < 4; ++j) v[j] = reinterpret_cast<const float4*>(ap)[j];
        }
        char* arow_hi = smem + (size_t)ar * LDS_STRIDE_B + ac0 * 2;
        #pragma unroll
        for (int j = 0; j < 4; ++j) {
            uint32_t h0 = pack_hi(v[j].x, v[j].y), h1 = pack_hi(v[j].z, v[j].w);
            uint32_t l0 = pack_lo(v[j].x, v[j].y, h0), l1 = pack_lo(v[j].z, v[j].w, h1);
            *reinterpret_cast<uint2*>(arow_hi + j * 8)           = make_uint2(h0, h1);
            *reinterpret_cast<uint2*>(arow_hi + OFF_ALO + j * 8) = make_uint2(l0, l1);
        }
        // B: cp.async, chunk 0 (koff = 0)
        const char* srch = (const char*)(g_Whi + (size_t)bgn * K_TOTAL) + bseg * 16;
        const char* srcl = (const char*)(g_Wlo + (size_t)bgn * K_TOTAL) + bseg * 16;
        uint32_t bdst = sb + OFF_BHI + br * LDS_STRIDE_B + bseg * 16;
        cp_async16(bdst,                            srch);
        cp_async16(bdst + (OFF_BLO - OFF_BHI),      srcl);
        cp_commit();
    }

    // ---- main loop ----
    #pragma unroll 1
    for (int c = 0; c < NCHUNK; ++c) {
        const int st = c & 1;
        const bool have = (c + 1 < NCHUNK);

        // LDG A(c+1) into regs (long latency, covered by compute below)
        float4 v[4] = {};
        if (have) {
            const int nc = c + 1, tap = nc >> 2, kc = (nc & 3) << 5;
            const int iy = aoy + tap / 3 - 1, ix = aox + tap % 3 - 1;
            if (((unsigned)iy < 128u) && ((unsigned)ix < 128u)) {
                const float* ap = feats +
                    ((size_t)(((ab << 7) + iy) << 7) + ix) * CIN + kc + ac0;
                #pragma unroll
                for (int j = 0; j < 4; ++j) v[j] = reinterpret_cast<const float4*>(ap)[j];
            }
        }

        cp_wait_all();
        __syncthreads();

        // issue B cp.async for (c+1) into the other stage
        if (have) {
            const int nc = c + 1, tap = nc >> 2, kc = (nc & 3) << 5;
            const int nst = nc & 1;
            const uint32_t bko = (uint32_t)tap * 128 + kc;
            const char* srch = (const char*)(g_Whi + (size_t)bgn * K_TOTAL + bko) + bseg * 16;
            const char* srcl = (const char*)(g_Wlo + (size_t)bgn * K_TOTAL + bko) + bseg * 16;
            uint32_t bdst = sb + nst * STAGE_BYTES + OFF_BHI + br * LDS_STRIDE_B + bseg * 16;
            cp_async16(bdst,                       srch);
            cp_async16(bdst + (OFF_BLO - OFF_BHI), srcl);
            cp_commit();
        }

        // ---- compute chunk c from stage st ----
        {
            const uint32_t a_s = sb + st * STAGE_BYTES;
            #pragma unroll
            for (int k16 = 0; k16 < 2; ++k16) {
                const int kb = k16 * 16;
                // A fragments (hi & lo) for both m16 tiles
                uint32_t ahi[2][4], alo[2][4];
                #pragma unroll
                for (int mt = 0; mt < 2; ++mt) {
                    const int arow = wm * 32 + mt * 16 + (l & 15);
                    const int acol = kb + (l >> 4) * 8;
                    const uint32_t aaddr = a_s + arow * LDS_STRIDE_B + acol * 2;
                    ldsm_x4(ahi[mt][0], ahi[mt][1], ahi[mt][2], ahi[mt][3], aaddr);
                    ldsm_x4(alo[mt][0], alo[mt][1], alo[mt][2], alo[mt][3], aaddr + OFF_ALO);
                }
                #pragma unroll
                for (int np = 0; np < 2; ++np) {
                    const int brow = wn * 32 + np * 16 + ((l >> 4) << 3) + (l & 7);
                    const int bcol = kb + ((l >> 3) & 1) * 8;
                    const uint32_t baddr = a_s + OFF_BHI + brow * LDS_STRIDE_B + bcol * 2;
                    uint32_t bh[4], bl[4];
                    ldsm_x4(bh[0], bh[1], bh[2], bh[3], baddr);
                    ldsm_x4(bl[0], bl[1], bl[2], bl[3], baddr + (OFF_BLO - OFF_BHI));
                    #pragma unroll
                    for (int mt = 0; mt < 2; ++mt) {
                        #pragma unroll
                        for (int sub = 0; sub < 2; ++sub) {
                            float* a4 = acc[mt][np * 2 + sub];
                            mma16816(a4, ahi[mt], bh[sub * 2], bh[sub * 2 + 1]);
                            mma16816(a4, ahi[mt], bl[sub * 2], bl[sub * 2 + 1]);
                            mma16816(a4, alo[mt], bh[sub * 2], bh[sub * 2 + 1]);
                        }
                    }
                }
            }
        }

        // ---- convert + STS A(c+1) into the other stage ----
        if (have) {
            const int nst = (c + 1) & 1;
            char* arow_hi = smem + (size_t)nst * STAGE_BYTES +
                            (size_t)ar * LDS_STRIDE_B + ac0 * 2;
            #pragma unroll
            for (int j = 0; j < 4; ++j) {
                uint32_t h0 = pack_hi(v[j].x, v[j].y), h1 = pack_hi(v[j].z, v[j].w);
                uint32_t l0 = pack_lo(v[j].x, v[j].y, h0), l1 = pack_lo(v[j].z, v[j].w, h1);
                *reinterpret_cast<uint2*>(arow_hi + j * 8)           = make_uint2(h0, h1);
                *reinterpret_cast<uint2*>(arow_hi + OFF_ALO + j * 8) = make_uint2(l0, l1);
            }
        }
    }

    // ---- epilogue ----
    const int row_base = mblk * 128 + wm * 32 + (l >> 2);
    const int col_base = nblk * 64 + wn * 32 + (l & 3) * 2;
    #pragma unroll
    for (int mt = 0; mt < 2; ++mt) {
        #pragma unroll
        for (int nt = 0; nt < 4; ++nt) {
            const int r0 = row_base + mt * 16;
            const int cc = col_base + nt * 8;
            float* o0 = out + (size_t)r0 * COUT + cc;
            float* o1 = out + (size_t)(r0 + 8) * COUT + cc;
            *reinterpret_cast<float2*>(o0) = make_float2(acc[mt][nt][0], acc[mt][nt][1]);
            *reinterpret_cast<float2*>(o1) = make_float2(acc[mt][nt][2], acc[mt][nt][3]);
        }
    }
}

// ---------------- launch ----------------
extern "C" void kernel_launch(void* const* d_in, const int* in_sizes, int n_in,
                              void* d_out, int out_size)
{
    const float* feats  = (const float*)d_in[0];
    const float* weight = (const float*)d_in[1];
    const float* alpha  = (const float*)d_in[2];
    float* out = (float*)d_out;

    cudaFuncSetAttribute(conv_mma_kernel,
                         cudaFuncAttributeMaxDynamicSharedMemorySize, SMEM_TOTAL);

    wconv_kernel<<<(K_TOTAL * COUT + 255) / 256, 256>>>(weight);
    dim3 grid(M_TOTAL / BM, COUT / BN);   // (256, 4)
    conv_mma_kernel<<<grid, NTHREADS, SMEM_TOTAL>>>(feats, alpha, out);
}